// round 6
// baseline (speedup 1.0000x reference)
#include <cuda_runtime.h>
#include <math.h>

#define NK     10000
#define SEQ    512
#define XS_POS 1792                      // worst read = 1023 + pad + (M-1)d <= 1791 (guarded)
#define SMEM_BYTES (XS_POS * 8 * 4)      // 57344 B dynamic shared
#define NT     256
#define NBLK   592                       // 4 CTAs/SM * 148 SMs

typedef unsigned long long ull;

__device__ int   g_ctr;
__device__ float g_par[NK * 16];         // 64B/item: {-w[0..10], -bias, dil, lo, pad, k}

// ---- prep: pack params, detect k, compute pad, negate; also resets the work counter ----
__global__ void prep_kernel(const float* __restrict__ W, const float* __restrict__ Bias,
                            const int* __restrict__ dil_, const int* __restrict__ lo_) {
    int i = blockIdx.x * blockDim.x + threadIdx.x;
    if (i == 0) g_ctr = 0;
    if (i >= NK) return;
    float w[11];
#pragma unroll
    for (int j = 0; j < 11; ++j) w[j] = W[i * 11 + j];
    int k = 11;
    if (w[9] == 0.f && w[10] == 0.f) k = 9;
    if (w[7] == 0.f && w[8] == 0.f) k = 7;
    const int dil = dil_[i], lo = lo_[i];
    const int pad = (lo - SEQ + dil * (k - 1)) >> 1;    // exact: lo = 512 + 2*pad - dil*(k-1)
    float* p = g_par + i * 16;
#pragma unroll
    for (int j = 0; j < 11; ++j) p[j] = -w[j];
    p[11] = -Bias[i];
    reinterpret_cast<int*>(p)[12] = dil;
    reinterpret_cast<int*>(p)[13] = lo;
    reinterpret_cast<int*>(p)[14] = pad;
    reinterpret_cast<int*>(p)[15] = k;
}

static __device__ __forceinline__ ull pack2(float a, float b) {
    ull r; asm("mov.b64 %0, {%1, %2};" : "=l"(r) : "f"(a), "f"(b)); return r;
}
static __device__ __forceinline__ void unpack2(ull v, float& a, float& b) {
    asm("mov.b64 {%0, %1}, %2;" : "=f"(a), "=f"(b) : "l"(v));
}
static __device__ __forceinline__ ull fma2(ull a, ull b, ull c) {
    ull r; asm("fma.rn.f32x2 %0, %1, %2, %3;" : "=l"(r) : "l"(a), "l"(b), "l"(c)); return r;
}
static __device__ __forceinline__ unsigned redux_min_u32(unsigned v, unsigned mask) {
    unsigned r; asm("redux.sync.min.u32 %0, %1, %2;" : "=r"(r) : "r"(v), "r"(mask)); return r;
}
static __device__ __forceinline__ unsigned redux_add_u32(unsigned v, unsigned mask) {
    unsigned r; asm("redux.sync.add.u32 %0, %1, %2;" : "=r"(r) : "r"(v), "r"(mask)); return r;
}
// order-preserving f32 -> u32 (total order; min_u32 == min_float)
static __device__ __forceinline__ unsigned flt2ord(float f) {
    unsigned u = __float_as_uint(f);
    return u ^ ((unsigned)((int)u >> 31) | 0x80000000u);
}
static __device__ __forceinline__ float ord2flt(unsigned t) {
    unsigned u = t ^ (((int)t < 0) ? 0x80000000u : 0xFFFFFFFFu);
    return __uint_as_float(u);
}

// Process rocket conv-kernel i, compile-time tap count K and tile height M.
// Lanes: c = lane>>1 (16 tile-lanes), h = lane&1 (batch half). Tile = M chain-
// consecutive outputs t0..t0+(M-1)d sharing K+M-1 loads. Weights/bias arrive
// pre-negated: accumulates s' = -s; max s = -min s'; ppv count via sign bits.
// SAFETY: caller guarantees pad + (M-1)*dil <= 768.
template<int K, int M>
static __device__ __forceinline__ void process_i(
    const ulonglong2* __restrict__ xsu, int i, int c, int h,
    const float* __restrict__ wng, float biasng, int dil, int lo, int pad,
    float* __restrict__ out)
{
    ull wn[K];
#pragma unroll
    for (int j = 0; j < K; ++j) wn[j] = pack2(wng[j], wng[j]);
    const ull biasn = pack2(biasng, biasng);

    const int dM = dil * M;
    const int stripes = (lo + dM - 1) / dM;            // once per item, warp-uniform
    const int ntiles = stripes * dil;
    const float inv_d = 1.0f / (float)dil;
    const int inc = dil * 2;                           // ulonglong2-index step per tap
    const int base0 = (SEQ - pad) * 2 + h;

    float mn0 = INFINITY, mn1 = INFINITY, mn2 = INFINITY, mn3 = INFINITY;
    unsigned cn0 = 0u, cn1 = 0u, cn2 = 0u, cn3 = 0u;

    for (int j = c; j < ntiles; j += 16) {
        // (stripe, off) = (j / dil, j % dil) via float reciprocal + correction
        int stripe = __float2int_rd(__int2float_rn(j) * inv_d);
        int off = j - stripe * dil;
        if (off < 0)         { --stripe; off += dil; }
        else if (off >= dil) { ++stripe; off -= dil; }
        const int t0 = stripe * dM + off;
        if (t0 >= lo) continue;

        int idx = base0 + t0 * 2;
        ull aL[M], aH[M];
#pragma unroll
        for (int q = 0; q < M; ++q) { aL[q] = biasn; aH[q] = biasn; }

#pragma unroll
        for (int v = 0; v < K + M - 1; ++v) {
            const int ph = idx ^ ((idx >> 3) & 6);     // bank swizzle within 128B row
            const ulonglong2 L = xsu[ph];
#pragma unroll
            for (int q = 0; q < M; ++q) {
                const int jj = v - q;
                if (jj >= 0 && jj < K) {
                    aL[q] = fma2(wn[jj], L.x, aL[q]);
                    aH[q] = fma2(wn[jj], L.y, aH[q]);
                }
            }
            idx += inc;
        }

#pragma unroll
        for (int q = 0; q < M; ++q) {
            if (t0 + q * dil < lo) {
                float s0, s1, s2, s3;
                unpack2(aL[q], s0, s1);
                unpack2(aH[q], s2, s3);
                mn0 = fminf(mn0, s0);  cn0 += __float_as_uint(s0) >> 31;
                mn1 = fminf(mn1, s1);  cn1 += __float_as_uint(s1) >> 31;
                mn2 = fminf(mn2, s2);  cn2 += __float_as_uint(s2) >> 31;
                mn3 = fminf(mn3, s3);  cn3 += __float_as_uint(s3) >> 31;
            }
        }
    }

    // reduce across the 16 tile-lanes of this h-group via REDUX
    const unsigned rmask = 0x55555555u << h;
    unsigned c01 = redux_add_u32(cn0 | (cn1 << 16), rmask);   // counts <= 1022, no carry
    unsigned c23 = redux_add_u32(cn2 | (cn3 << 16), rmask);
    unsigned t0o = redux_min_u32(flt2ord(mn0), rmask);
    unsigned t1o = redux_min_u32(flt2ord(mn1), rmask);
    unsigned t2o = redux_min_u32(flt2ord(mn2), rmask);
    unsigned t3o = redux_min_u32(flt2ord(mn3), rmask);

    if (c == 0) {
        const float il = 1.f / (float)lo;
        float2* o2 = reinterpret_cast<float2*>(out);
        o2[(4 * h + 0) * NK + i] = make_float2(-ord2flt(t0o), (float)(c01 & 0xFFFFu) * il);
        o2[(4 * h + 1) * NK + i] = make_float2(-ord2flt(t1o), (float)(c01 >> 16) * il);
        o2[(4 * h + 2) * NK + i] = make_float2(-ord2flt(t2o), (float)(c23 & 0xFFFFu) * il);
        o2[(4 * h + 3) * NK + i] = make_float2(-ord2flt(t3o), (float)(c23 >> 16) * il);
    }
}

__global__ __launch_bounds__(NT, 4)
void rocket_kernel(const float* __restrict__ x,     // (8,1,512)
                   float*       __restrict__ out)   // (8, 20000) interleaved (max, ppv)
{
    extern __shared__ float xs[];   // swizzled [pos][8 batches], zero-padded
    const int tid = threadIdx.x;

    // zero fill
    float4* z4 = reinterpret_cast<float4*>(xs);
#pragma unroll
    for (int t = tid; t < XS_POS * 8 / 4; t += NT)
        z4[t] = make_float4(0.f, 0.f, 0.f, 0.f);
    __syncthreads();

    // transpose-load x with swizzle: logical xs[(s+512)*8 + b]
    for (int t = tid; t < 8 * SEQ; t += NT) {
        int b = t >> 9;
        int s = t & 511;
        int idx4 = (s + SEQ) * 2 + (b >> 2);
        int ph = idx4 ^ ((idx4 >> 3) & 6);
        xs[ph * 4 + (b & 3)] = x[t];
    }
    __syncthreads();

    const int lane = tid & 31;
    const int c = lane >> 1;
    const int h = lane & 1;
    const ulonglong2* xsu = reinterpret_cast<const ulonglong2*>(xs);

    int i;
    if (lane == 0) i = atomicAdd(&g_ctr, 1);
    i = __shfl_sync(0xffffffffu, i, 0);

    while (i < NK) {
        // pipeline: steal next item now (ATOMG overlaps this item's compute),
        // prefetch its param line into L1.
        int inext;
        if (lane == 0) inext = atomicAdd(&g_ctr, 1);
        inext = __shfl_sync(0xffffffffu, inext, 0);
        if (inext < NK)
            asm volatile("prefetch.global.L1 [%0];" :: "l"(g_par + inext * 16));

        const float4* pp = reinterpret_cast<const float4*>(g_par + i * 16);
        const float4 q0 = __ldg(pp + 0);
        const float4 q1 = __ldg(pp + 1);
        const float4 q2 = __ldg(pp + 2);
        const float4 q3 = __ldg(pp + 3);
        const float wng[11] = {q0.x, q0.y, q0.z, q0.w, q1.x, q1.y, q1.z, q1.w,
                               q2.x, q2.y, q2.z};
        const float bng = q2.w;
        const int dil = __float_as_int(q3.x);
        const int lo  = __float_as_int(q3.y);
        const int pad = __float_as_int(q3.z);
        const int k   = __float_as_int(q3.w);

        if (k == 7) {
            if (pad + 5 * dil <= 768)   // M=6 tile stays inside XS_POS
                process_i<7, 6>(xsu, i, c, h, wng, bng, dil, lo, pad, out);
            else
                process_i<7, 4>(xsu, i, c, h, wng, bng, dil, lo, pad, out);
        } else if (k == 9) {
            process_i<9, 5>(xsu, i, c, h, wng, bng, dil, lo, pad, out);  // pad+4d <= 759
        } else {
            process_i<11, 4>(xsu, i, c, h, wng, bng, dil, lo, pad, out); // pad+3d <= 663
        }
        i = inext;
    }
}

extern "C" void kernel_launch(void* const* d_in, const int* in_sizes, int n_in,
                              void* d_out, int out_size) {
    const float* x    = (const float*)d_in[0];  // (8,1,512)
    const float* Wt   = (const float*)d_in[1];  // (10000,1,11)
    const float* Bias = (const float*)d_in[2];  // (10000,)
    // d_in[3] = base (unused: pad recovered from lo/dil/k)
    const int*   dil  = (const int*)d_in[4];
    const int*   lo   = (const int*)d_in[5];
    float* out = (float*)d_out;                 // (8, 20000)

    cudaFuncSetAttribute(rocket_kernel,
                         cudaFuncAttributeMaxDynamicSharedMemorySize, SMEM_BYTES);
    prep_kernel<<<(NK + 255) / 256, 256>>>(Wt, Bias, dil, lo);
    rocket_kernel<<<NBLK, NT, SMEM_BYTES>>>(x, out);
}

// round 7
// speedup vs baseline: 1.0007x; 1.0007x over previous
#include <cuda_runtime.h>
#include <math.h>

#define NK     10000
#define SEQ    512
#define XS_POS 1792                      // worst read = 1023 + pad + (M-1)d <= 1791 (guarded)
#define SMEM_BYTES (XS_POS * 8 * 4)      // 57344 B dynamic shared
#define NT     256
#define NBLK   592                       // 4 CTAs/SM * 148 SMs

typedef unsigned long long ull;

__device__ int   g_ctr;
__device__ int   g_heavy_cur;
__device__ int   g_light_cur;
__device__ int   g_perm[NK];             // heavy-first steal order
__device__ float g_par[NK * 16];         // 64B/item: {-w[0..10], -bias, dil, lo, pad, k}

__global__ void reset_kernel() {
    g_ctr = 0;
    g_heavy_cur = 0;
    g_light_cur = NK - 1;
}

// prep: pack params, detect k, compute pad, negate; classify into heavy/light order
__global__ void prep_kernel(const float* __restrict__ W, const float* __restrict__ Bias,
                            const int* __restrict__ dil_, const int* __restrict__ lo_) {
    int i = blockIdx.x * blockDim.x + threadIdx.x;
    if (i >= NK) return;
    float w[11];
#pragma unroll
    for (int j = 0; j < 11; ++j) w[j] = W[i * 11 + j];
    int k = 11;
    if (w[9] == 0.f && w[10] == 0.f) k = 9;
    if (w[7] == 0.f && w[8] == 0.f) k = 7;
    const int dil = dil_[i], lo = lo_[i];
    const int pad = (lo - SEQ + dil * (k - 1)) >> 1;    // exact: lo = 512 + 2*pad - dil*(k-1)
    float* p = g_par + i * 16;
#pragma unroll
    for (int j = 0; j < 11; ++j) p[j] = -w[j];
    p[11] = -Bias[i];
    reinterpret_cast<int*>(p)[12] = dil;
    reinterpret_cast<int*>(p)[13] = lo;
    reinterpret_cast<int*>(p)[14] = pad;
    reinterpret_cast<int*>(p)[15] = k;
    // heavy items first in steal order; light items fill the tail
    int slot;
    if (lo * k >= 2560) slot = atomicAdd(&g_heavy_cur, 1);
    else                slot = atomicAdd(&g_light_cur, -1);
    g_perm[slot] = i;
}

static __device__ __forceinline__ ull pack2(float a, float b) {
    ull r; asm("mov.b64 %0, {%1, %2};" : "=l"(r) : "f"(a), "f"(b)); return r;
}
static __device__ __forceinline__ void unpack2(ull v, float& a, float& b) {
    asm("mov.b64 {%0, %1}, %2;" : "=f"(a), "=f"(b) : "l"(v));
}
static __device__ __forceinline__ ull fma2(ull a, ull b, ull c) {
    ull r; asm("fma.rn.f32x2 %0, %1, %2, %3;" : "=l"(r) : "l"(a), "l"(b), "l"(c)); return r;
}

// Process rocket conv-kernel i, compile-time tap count K and tile height M.
// Lanes: c = lane>>1 (16 tile-lanes), h = lane&1 (batch half). Tile = M chain-
// consecutive outputs t0..t0+(M-1)d sharing K+M-1 loads. Weights/bias arrive
// pre-negated: accumulates s' = -s; max s = -min s'; ppv count via sign bits.
// SAFETY: caller guarantees pad + (M-1)*dil <= 768.
template<int K, int M>
static __device__ __forceinline__ void process_i(
    const ulonglong2* __restrict__ xsu, int i, int c, int h,
    const float* __restrict__ wng, float biasng, int dil, int lo, int pad,
    float* __restrict__ out)
{
    ull wn[K];
#pragma unroll
    for (int j = 0; j < K; ++j) wn[j] = pack2(wng[j], wng[j]);
    const ull biasn = pack2(biasng, biasng);

    const int dM = dil * M;
    const int stripes = (lo + dM - 1) / dM;            // once per item, warp-uniform
    const int ntiles = stripes * dil;
    const float inv_d = 1.0f / (float)dil;
    const int inc = dil * 2;                           // ulonglong2-index step per tap
    const int base0 = (SEQ - pad) * 2 + h;

    float mn0 = INFINITY, mn1 = INFINITY, mn2 = INFINITY, mn3 = INFINITY;
    unsigned cn0 = 0u, cn1 = 0u, cn2 = 0u, cn3 = 0u;

    for (int j = c; j < ntiles; j += 16) {
        // (stripe, off) = (j / dil, j % dil) via float reciprocal + correction
        int stripe = __float2int_rd(__int2float_rn(j) * inv_d);
        int off = j - stripe * dil;
        if (off < 0)         { --stripe; off += dil; }
        else if (off >= dil) { ++stripe; off -= dil; }
        const int t0 = stripe * dM + off;
        if (t0 >= lo) continue;

        int idx = base0 + t0 * 2;
        ull aL[M], aH[M];
#pragma unroll
        for (int q = 0; q < M; ++q) { aL[q] = biasn; aH[q] = biasn; }

#pragma unroll
        for (int v = 0; v < K + M - 1; ++v) {
            const int ph = idx ^ ((idx >> 3) & 6);     // bank swizzle within 128B row
            const ulonglong2 L = xsu[ph];
#pragma unroll
            for (int q = 0; q < M; ++q) {
                const int jj = v - q;
                if (jj >= 0 && jj < K) {
                    aL[q] = fma2(wn[jj], L.x, aL[q]);
                    aH[q] = fma2(wn[jj], L.y, aH[q]);
                }
            }
            idx += inc;
        }

#pragma unroll
        for (int q = 0; q < M; ++q) {
            if (t0 + q * dil < lo) {
                float s0, s1, s2, s3;
                unpack2(aL[q], s0, s1);
                unpack2(aH[q], s2, s3);
                mn0 = fminf(mn0, s0);  cn0 += __float_as_uint(s0) >> 31;
                mn1 = fminf(mn1, s1);  cn1 += __float_as_uint(s1) >> 31;
                mn2 = fminf(mn2, s2);  cn2 += __float_as_uint(s2) >> 31;
                mn3 = fminf(mn3, s3);  cn3 += __float_as_uint(s3) >> 31;
            }
        }
    }

    // reduce across the 16 tile-lanes (xor offsets 2..16 keep h fixed);
    // counts packed 2x16-bit (max 1022 each, no carry)
    unsigned p01 = cn0 | (cn1 << 16);
    unsigned p23 = cn2 | (cn3 << 16);
#pragma unroll
    for (int off = 2; off < 32; off <<= 1) {
        mn0 = fminf(mn0, __shfl_xor_sync(0xffffffffu, mn0, off));
        mn1 = fminf(mn1, __shfl_xor_sync(0xffffffffu, mn1, off));
        mn2 = fminf(mn2, __shfl_xor_sync(0xffffffffu, mn2, off));
        mn3 = fminf(mn3, __shfl_xor_sync(0xffffffffu, mn3, off));
        p01 += __shfl_xor_sync(0xffffffffu, p01, off);
        p23 += __shfl_xor_sync(0xffffffffu, p23, off);
    }

    if (c == 0) {
        const float il = 1.f / (float)lo;
        float2* o2 = reinterpret_cast<float2*>(out);
        o2[(4 * h + 0) * NK + i] = make_float2(-mn0, (float)(p01 & 0xFFFFu) * il);
        o2[(4 * h + 1) * NK + i] = make_float2(-mn1, (float)(p01 >> 16) * il);
        o2[(4 * h + 2) * NK + i] = make_float2(-mn2, (float)(p23 & 0xFFFFu) * il);
        o2[(4 * h + 3) * NK + i] = make_float2(-mn3, (float)(p23 >> 16) * il);
    }
}

__global__ __launch_bounds__(NT, 4)
void rocket_kernel(const float* __restrict__ x,     // (8,1,512)
                   float*       __restrict__ out)   // (8, 20000) interleaved (max, ppv)
{
    extern __shared__ float xs[];   // swizzled [pos][8 batches], zero-padded
    const int tid = threadIdx.x;

    // zero fill
    float4* z4 = reinterpret_cast<float4*>(xs);
#pragma unroll
    for (int t = tid; t < XS_POS * 8 / 4; t += NT)
        z4[t] = make_float4(0.f, 0.f, 0.f, 0.f);
    __syncthreads();

    // transpose-load x with swizzle: logical xs[(s+512)*8 + b]
    for (int t = tid; t < 8 * SEQ; t += NT) {
        int b = t >> 9;
        int s = t & 511;
        int idx4 = (s + SEQ) * 2 + (b >> 2);
        int ph = idx4 ^ ((idx4 >> 3) & 6);
        xs[ph * 4 + (b & 3)] = x[t];
    }
    __syncthreads();

    const int lane = tid & 31;
    const int c = lane >> 1;
    const int h = lane & 1;
    const ulonglong2* xsu = reinterpret_cast<const ulonglong2*>(xs);

    int slot;
    if (lane == 0) slot = atomicAdd(&g_ctr, 1);
    slot = __shfl_sync(0xffffffffu, slot, 0);
    int i = (slot < NK) ? __ldg(&g_perm[slot]) : NK;

    while (i < NK) {
        // pipeline: steal next slot now (ATOMG overlaps this item's compute),
        // resolve its index and prefetch its param line into L1.
        int snext;
        if (lane == 0) snext = atomicAdd(&g_ctr, 1);
        snext = __shfl_sync(0xffffffffu, snext, 0);
        int inext = NK;
        if (snext < NK) {
            inext = __ldg(&g_perm[snext]);
            asm volatile("prefetch.global.L1 [%0];" :: "l"(g_par + inext * 16));
        }

        const float4* pp = reinterpret_cast<const float4*>(g_par + i * 16);
        const float4 q0 = __ldg(pp + 0);
        const float4 q1 = __ldg(pp + 1);
        const float4 q2 = __ldg(pp + 2);
        const float4 q3 = __ldg(pp + 3);
        const float wng[11] = {q0.x, q0.y, q0.z, q0.w, q1.x, q1.y, q1.z, q1.w,
                               q2.x, q2.y, q2.z};
        const float bng = q2.w;
        const int dil = __float_as_int(q3.x);
        const int lo  = __float_as_int(q3.y);
        const int pad = __float_as_int(q3.z);
        const int k   = __float_as_int(q3.w);

        if (k == 7) {
            if (pad + 5 * dil <= 768)   // M=6 tile stays inside XS_POS
                process_i<7, 6>(xsu, i, c, h, wng, bng, dil, lo, pad, out);
            else
                process_i<7, 4>(xsu, i, c, h, wng, bng, dil, lo, pad, out);
        } else if (k == 9) {
            process_i<9, 5>(xsu, i, c, h, wng, bng, dil, lo, pad, out);  // pad+4d <= 759
        } else {
            process_i<11, 4>(xsu, i, c, h, wng, bng, dil, lo, pad, out); // pad+3d <= 663
        }
        i = inext;
    }
}

extern "C" void kernel_launch(void* const* d_in, const int* in_sizes, int n_in,
                              void* d_out, int out_size) {
    const float* x    = (const float*)d_in[0];  // (8,1,512)
    const float* Wt   = (const float*)d_in[1];  // (10000,1,11)
    const float* Bias = (const float*)d_in[2];  // (10000,)
    // d_in[3] = base (unused: pad recovered from lo/dil/k)
    const int*   dil  = (const int*)d_in[4];
    const int*   lo   = (const int*)d_in[5];
    float* out = (float*)d_out;                 // (8, 20000)

    cudaFuncSetAttribute(rocket_kernel,
                         cudaFuncAttributeMaxDynamicSharedMemorySize, SMEM_BYTES);
    reset_kernel<<<1, 1>>>();
    prep_kernel<<<(NK + 255) / 256, 256>>>(Wt, Bias, dil, lo);
    rocket_kernel<<<NBLK, NT, SMEM_BYTES>>>(x, out);
}

// round 8
// speedup vs baseline: 1.2732x; 1.2723x over previous
#include <cuda_runtime.h>
#include <math.h>

#define NK     10000
#define SEQ    512
#define XS_POS 1792                      // worst read = 1023 + pad + (M-1)d <= 1791 (guarded)
#define SMEM_BYTES (XS_POS * 8 * 4)      // 57344 B dynamic shared
#define NT     256
#define NBLK   592                       // 4 CTAs/SM * 148 SMs, all resident
#define TOTAL_WARPS (NBLK * (NT / 32))   // 4736

typedef unsigned long long ull;

__device__ int g_ctr;                    // work-steal cursor (self-resetting)
__device__ int g_done;                   // finished-warp count (self-resetting)

static __device__ __forceinline__ ull pack2(float a, float b) {
    ull r; asm("mov.b64 %0, {%1, %2};" : "=l"(r) : "f"(a), "f"(b)); return r;
}
static __device__ __forceinline__ void unpack2(ull v, float& a, float& b) {
    asm("mov.b64 {%0, %1}, %2;" : "=f"(a), "=f"(b) : "l"(v));
}
static __device__ __forceinline__ ull fma2(ull a, ull b, ull c) {
    ull r; asm("fma.rn.f32x2 %0, %1, %2, %3;" : "=l"(r) : "l"(a), "l"(b), "l"(c)); return r;
}

// Process rocket conv-kernel i with compile-time tap count K and tile height M.
// Lanes: c = lane>>1 (16 tile-lanes), h = lane&1 (batch half). Tile = M chain-
// consecutive outputs t0..t0+(M-1)d sharing K+M-1 loads. Accumulates s' = -s:
// max s = -min s'; ppv count = #(s' < 0) via sign bits.
// SAFETY: caller guarantees pad + (M-1)*dil <= 768 so all reads < XS_POS.
template<int K, int M>
static __device__ __forceinline__ void process_i(
    const ulonglong2* __restrict__ xsu, int i, int c, int h,
    const float* __restrict__ w, float bias, int dil, int lo, int pad,
    float* __restrict__ out)
{
    ull wn[K];
#pragma unroll
    for (int j = 0; j < K; ++j) wn[j] = pack2(-w[j], -w[j]);
    const ull biasn = pack2(-bias, -bias);

    const int dM = dil * M;
    const int stripes = (lo + dM - 1) / dM;            // once per item, warp-uniform
    const int ntiles = stripes * dil;
    const float inv_d = 1.0f / (float)dil;
    const int inc = dil * 2;                           // ulonglong2-index step per tap
    const int base0 = (SEQ - pad) * 2 + h;

    float mn0 = INFINITY, mn1 = INFINITY, mn2 = INFINITY, mn3 = INFINITY;
    unsigned cn0 = 0u, cn1 = 0u, cn2 = 0u, cn3 = 0u;

    for (int j = c; j < ntiles; j += 16) {
        // (stripe, off) = (j / dil, j % dil) via float reciprocal + correction
        int stripe = __float2int_rd(__int2float_rn(j) * inv_d);
        int off = j - stripe * dil;
        if (off < 0)         { --stripe; off += dil; }
        else if (off >= dil) { ++stripe; off -= dil; }
        const int t0 = stripe * dM + off;
        if (t0 >= lo) continue;

        int idx = base0 + t0 * 2;
        ull aL[M], aH[M];
#pragma unroll
        for (int q = 0; q < M; ++q) { aL[q] = biasn; aH[q] = biasn; }

#pragma unroll
        for (int v = 0; v < K + M - 1; ++v) {
            const int ph = idx ^ ((idx >> 3) & 6);     // bank swizzle within 128B row
            const ulonglong2 L = xsu[ph];
#pragma unroll
            for (int q = 0; q < M; ++q) {
                const int jj = v - q;
                if (jj >= 0 && jj < K) {
                    aL[q] = fma2(wn[jj], L.x, aL[q]);
                    aH[q] = fma2(wn[jj], L.y, aH[q]);
                }
            }
            idx += inc;
        }

#pragma unroll
        for (int q = 0; q < M; ++q) {
            if (t0 + q * dil < lo) {
                float s0, s1, s2, s3;
                unpack2(aL[q], s0, s1);
                unpack2(aH[q], s2, s3);
                mn0 = fminf(mn0, s0);  cn0 += __float_as_uint(s0) >> 31;
                mn1 = fminf(mn1, s1);  cn1 += __float_as_uint(s1) >> 31;
                mn2 = fminf(mn2, s2);  cn2 += __float_as_uint(s2) >> 31;
                mn3 = fminf(mn3, s3);  cn3 += __float_as_uint(s3) >> 31;
            }
        }
    }

    // reduce across the 16 tile-lanes (xor offsets 2..16 keep h fixed);
    // counts packed 2x16-bit (max 1022 each, no carry)
    unsigned p01 = cn0 | (cn1 << 16);
    unsigned p23 = cn2 | (cn3 << 16);
#pragma unroll
    for (int off = 2; off < 32; off <<= 1) {
        mn0 = fminf(mn0, __shfl_xor_sync(0xffffffffu, mn0, off));
        mn1 = fminf(mn1, __shfl_xor_sync(0xffffffffu, mn1, off));
        mn2 = fminf(mn2, __shfl_xor_sync(0xffffffffu, mn2, off));
        mn3 = fminf(mn3, __shfl_xor_sync(0xffffffffu, mn3, off));
        p01 += __shfl_xor_sync(0xffffffffu, p01, off);
        p23 += __shfl_xor_sync(0xffffffffu, p23, off);
    }

    if (c == 0) {
        const float il = 1.f / (float)lo;
        float2* o2 = reinterpret_cast<float2*>(out);
        o2[(4 * h + 0) * NK + i] = make_float2(-mn0, (float)(p01 & 0xFFFFu) * il);
        o2[(4 * h + 1) * NK + i] = make_float2(-mn1, (float)(p01 >> 16) * il);
        o2[(4 * h + 2) * NK + i] = make_float2(-mn2, (float)(p23 & 0xFFFFu) * il);
        o2[(4 * h + 3) * NK + i] = make_float2(-mn3, (float)(p23 >> 16) * il);
    }
}

__global__ __launch_bounds__(NT, 4)
void rocket_kernel(const float* __restrict__ x,     // (8,1,512)
                   const float* __restrict__ W,     // (10000,1,11)
                   const float* __restrict__ Bias,  // (10000,)
                   const int*   __restrict__ dil_,  // (10000,)
                   const int*   __restrict__ lo_,   // (10000,)
                   float*       __restrict__ out)   // (8, 20000) interleaved (max, ppv)
{
    extern __shared__ float xs[];   // swizzled [pos][8 batches], zero-padded
    const int tid = threadIdx.x;

    // Prologue (single barrier): zero only the two pad regions, transpose x into
    // the middle. Regions are disjoint in idx4 space: pads = [0,1024)+[2048,3584),
    // transpose writes [1024,2048). Both pad ranges are 128B-row aligned, and the
    // swizzle permutes only within rows, so physical zeroing covers them exactly.
    float4* z4 = reinterpret_cast<float4*>(xs);
#pragma unroll
    for (int t = tid; t < 1024; t += NT)
        z4[t] = make_float4(0.f, 0.f, 0.f, 0.f);
#pragma unroll
    for (int t = tid; t < 1536; t += NT)
        z4[2048 + t] = make_float4(0.f, 0.f, 0.f, 0.f);
    for (int t = tid; t < 8 * SEQ; t += NT) {
        int b = t >> 9;
        int s = t & 511;
        int idx4 = (s + SEQ) * 2 + (b >> 2);
        int ph = idx4 ^ ((idx4 >> 3) & 6);
        xs[ph * 4 + (b & 3)] = x[t];
    }
    __syncthreads();

    const int lane = tid & 31;
    const int c = lane >> 1;
    const int h = lane & 1;
    const ulonglong2* xsu = reinterpret_cast<const ulonglong2*>(xs);

    while (true) {
        int i;
        if (lane == 0) i = atomicAdd(&g_ctr, 1);
        i = __shfl_sync(0xffffffffu, i, 0);
        if (i >= NK) break;

        float w[11];
        const float* wr = W + i * 11;
#pragma unroll
        for (int j = 0; j < 11; ++j) w[j] = __ldg(wr + j);
        const float bias = __ldg(Bias + i);
        const int   dil  = __ldg(dil_ + i);
        const int   lo   = __ldg(lo_ + i);

        // recover tap count from exact-zero weight tail
        if (w[7] == 0.f && w[8] == 0.f) {
            const int pad = (lo - SEQ + dil * 6) >> 1;
            if (pad + 5 * dil <= 768)   // M=6 tile stays inside XS_POS
                process_i<7, 6>(xsu, i, c, h, w, bias, dil, lo, pad, out);
            else
                process_i<7, 4>(xsu, i, c, h, w, bias, dil, lo, pad, out);
        } else if (w[9] == 0.f && w[10] == 0.f) {
            const int pad = (lo - SEQ + dil * 8) >> 1;   // pad+4d <= 759 always
            process_i<9, 5>(xsu, i, c, h, w, bias, dil, lo, pad, out);
        } else {
            const int pad = (lo - SEQ + dil * 10) >> 1;  // pad+3d <= 663 always
            process_i<11, 4>(xsu, i, c, h, w, bias, dil, lo, pad, out);
        }
    }

    // Self-resetting counters: a warp increments g_done only after its final
    // g_ctr atomic, so the last arrival implies all steals are done. Kernel
    // completion fences the stores for the next graph replay.
    if (lane == 0) {
        int d = atomicAdd(&g_done, 1);
        if (d == TOTAL_WARPS - 1) {
            g_ctr = 0;
            g_done = 0;
        }
    }
}

extern "C" void kernel_launch(void* const* d_in, const int* in_sizes, int n_in,
                              void* d_out, int out_size) {
    const float* x    = (const float*)d_in[0];  // (8,1,512)
    const float* Wt   = (const float*)d_in[1];  // (10000,1,11)
    const float* Bias = (const float*)d_in[2];  // (10000,)
    // d_in[3] = base (unused: pad recovered from lo/dil/k)
    const int*   dil  = (const int*)d_in[4];
    const int*   lo   = (const int*)d_in[5];
    float* out = (float*)d_out;                 // (8, 20000)

    cudaFuncSetAttribute(rocket_kernel,
                         cudaFuncAttributeMaxDynamicSharedMemorySize, SMEM_BYTES);
    rocket_kernel<<<NBLK, NT, SMEM_BYTES>>>(x, Wt, Bias, dil, lo, out);
}